// round 2
// baseline (speedup 1.0000x reference)
#include <cuda_runtime.h>
#include <cstdint>

// ---------------- problem constants ----------------
namespace {
constexpr int H_    = 10;
constexpr int NROWS = 100000;
constexpr int F_    = 256;
constexpr int HIDD  = 512;
constexpr int C_    = 47;

constexpr int BM = 128, BN = 128, BK = 16;
constexpr int ASTR = 20;    // padded A smem stride (conflict-free frag loads)
constexpr int BSTR = 136;   // padded B smem stride (conflict-free frag loads)
}

// ---------------- scratch (static device allocs are the sanctioned path) ----
__device__ float g_S1[(size_t)NROWS * HIDD];
__device__ float g_S2[(size_t)NROWS * HIDD];
__device__ float g_S3[(size_t)NROWS * HIDD];

// ---------------- helpers ----------------
__device__ __forceinline__ unsigned f2tf(float f) {
    unsigned u; asm("cvt.rna.tf32.f32 %0, %1;" : "=r"(u) : "f"(f)); return u;
}
__device__ __forceinline__ void mma_tf32(float* c, const unsigned* a, unsigned b0, unsigned b1) {
    asm volatile(
        "mma.sync.aligned.m16n8k8.row.col.f32.tf32.tf32.f32 "
        "{%0,%1,%2,%3},{%4,%5,%6,%7},{%8,%9},{%0,%1,%2,%3};"
        : "+f"(c[0]), "+f"(c[1]), "+f"(c[2]), "+f"(c[3])
        : "r"(a[0]), "r"(a[1]), "r"(a[2]), "r"(a[3]), "r"(b0), "r"(b1));
}

// ============================================================================
// Fused recursive attention: one warp per row n.
// Caches feat[h,n,:] (80 regs/lane), computes xl/xr via warp reductions,
// runs the 10-step recursive softmax in-register, writes right[n,:].
// Key identity: history@wl = sum_h att[h]*xl[h] -> no history materialization.
// ============================================================================
__global__ __launch_bounds__(256)
void att_kernel(const float* __restrict__ feat, const float* __restrict__ wa,
                const float* __restrict__ ba_p, float* __restrict__ right)
{
    const int gw   = (blockIdx.x * blockDim.x + threadIdx.x) >> 5;
    const int lane = threadIdx.x & 31;
    if (gw >= NROWS) return;

    const float ba = __ldg(ba_p);

    float wlv[8], wrv[8];
#pragma unroll
    for (int j = 0; j < 8; j++) {
        wlv[j] = __ldg(wa + lane + 32 * j);
        wrv[j] = __ldg(wa + F_ + lane + 32 * j);
    }

    // lane owns features f = lane + 32*j  (coalesced loads & stores)
    float v[H_][8];
    const float* base = feat + (size_t)gw * F_ + lane;
#pragma unroll
    for (int h = 0; h < H_; h++) {
        const float* p = base + (size_t)h * NROWS * F_;
#pragma unroll
        for (int j = 0; j < 8; j++) v[h][j] = p[32 * j];
    }

    float xl[H_], xr[H_];
#pragma unroll
    for (int h = 0; h < H_; h++) {
        float sl = 0.f, sr = 0.f;
#pragma unroll
        for (int j = 0; j < 8; j++) { sl = fmaf(v[h][j], wlv[j], sl); sr = fmaf(v[h][j], wrv[j], sr); }
#pragma unroll
        for (int o = 16; o; o >>= 1) {
            sl += __shfl_xor_sync(0xffffffffu, sl, o);
            sr += __shfl_xor_sync(0xffffffffu, sr, o);
        }
        xl[h] = sl; xr[h] = sr;
    }

    float s[H_];
    { float t = xl[0] + xr[0] + ba; s[0] = t >= 0.f ? t : 0.2f * t; }
#pragma unroll
    for (int i = 1; i < H_; i++) {
        float m = s[0];
        for (int h2 = 1; h2 < i; h2++) m = fmaxf(m, s[h2]);
        float den = 0.f, num = 0.f;
        for (int h2 = 0; h2 < i; h2++) {
            float e = __expf(s[h2] - m);
            den += e; num = fmaf(e, xl[h2], num);
        }
        float t = num / den + xr[i] + ba;
        s[i] = t >= 0.f ? t : 0.2f * t;
    }

    float m = s[0];
#pragma unroll
    for (int h2 = 1; h2 < H_; h2++) m = fmaxf(m, s[h2]);
    float e[H_], den = 0.f;
#pragma unroll
    for (int h2 = 0; h2 < H_; h2++) { e[h2] = __expf(s[h2] - m); den += e[h2]; }
    const float inv = 1.f / den;

    float* rp = right + (size_t)gw * F_ + lane;
#pragma unroll
    for (int j = 0; j < 8; j++) {
        float acc = 0.f;
#pragma unroll
        for (int h2 = 0; h2 < H_; h2++) acc = fmaf(e[h2] * inv, v[h2][j], acc);
        rp[32 * j] = acc;
    }
}

// ============================================================================
// 3xTF32 GEMM with fused A-transform and epilogue.
// ATR: 0 none | 1 prelu(alpha) | 2 support = 0.5*prelu(A,alpha)+0.5*A2
// EPI: 0 D=v+bias | 1 D=prelu(v+bias,alpha) | 2 D=v+prelu(X,alpha) | 3 D=X+v+bias
// ============================================================================
template<int ATR, int EPI>
__global__ __launch_bounds__(256)
void gemm_kernel(const float* __restrict__ A, const float* __restrict__ A2,
                 const float* __restrict__ B, const float* __restrict__ bias,
                 float* __restrict__ D, const float* __restrict__ X,
                 const float* __restrict__ alpha_p,
                 int M, int Nc, int K)
{
    __shared__ unsigned AsH[BM * ASTR];
    __shared__ unsigned AsL[BM * ASTR];
    __shared__ unsigned BsH[BK * BSTR];
    __shared__ unsigned BsL[BK * BSTR];

    const int tid  = threadIdx.x;
    const int warp = tid >> 5, lane = tid & 31;
    const int wr = warp >> 1, wc = warp & 1;
    const int g = lane >> 2, t4 = lane & 3;
    const int rowBase = blockIdx.y * BM;
    const int colBase = blockIdx.x * BN;

    float alpha = 0.f;
    if (ATR == 1 || ATR == 2 || EPI == 1 || EPI == 2) alpha = __ldg(alpha_p);

    const int lr = tid >> 4;   // 0..15
    const int lc = tid & 15;   // 0..15

    float acc[2][8][4];
#pragma unroll
    for (int mi = 0; mi < 2; mi++)
#pragma unroll
        for (int ni = 0; ni < 8; ni++)
#pragma unroll
            for (int q = 0; q < 4; q++) acc[mi][ni][q] = 0.f;

    float aReg[8], bReg[8];
    const int ktiles = (K + BK - 1) / BK;

    auto loadA = [&](int k0) {
#pragma unroll
        for (int j = 0; j < 8; j++) {
            int rr = rowBase + lr + 16 * j;
            int cc = k0 + lc;
            float v = 0.f;
            if (rr < M && cc < K) {
                if (ATR == 2) {
                    float xv = A[(size_t)rr * K + cc];
                    float hv = A2[(size_t)rr * K + cc];
                    float xi = xv >= 0.f ? xv : alpha * xv;
                    v = 0.5f * xi + 0.5f * hv;
                } else if (ATR == 1) {
                    float xv = A[(size_t)rr * K + cc];
                    v = xv >= 0.f ? xv : alpha * xv;
                } else {
                    v = A[(size_t)rr * K + cc];
                }
            }
            aReg[j] = v;
        }
    };
    auto loadB = [&](int k0) {
#pragma unroll
        for (int j = 0; j < 8; j++) {
            int rr = k0 + lr;
            int cc = colBase + lc + 16 * j;
            bReg[j] = (rr < K && cc < Nc) ? B[(size_t)rr * Nc + cc] : 0.f;
        }
    };
    auto stageSmem = [&]() {
#pragma unroll
        for (int j = 0; j < 8; j++) {
            float f = aReg[j];
            unsigned hi = f2tf(f);
            float lo = f - __uint_as_float(hi);
            AsH[(lr + 16 * j) * ASTR + lc] = hi;
            AsL[(lr + 16 * j) * ASTR + lc] = f2tf(lo);
        }
#pragma unroll
        for (int j = 0; j < 8; j++) {
            float f = bReg[j];
            unsigned hi = f2tf(f);
            float lo = f - __uint_as_float(hi);
            BsH[lr * BSTR + lc + 16 * j] = hi;
            BsL[lr * BSTR + lc + 16 * j] = f2tf(lo);
        }
    };

    loadA(0); loadB(0);
    stageSmem();
    __syncthreads();

    for (int kt = 0; kt < ktiles; kt++) {
        if (kt + 1 < ktiles) { loadA((kt + 1) * BK); loadB((kt + 1) * BK); }
#pragma unroll
        for (int kk = 0; kk < 2; kk++) {
            unsigned ah[2][4], al[2][4];
#pragma unroll
            for (int mi = 0; mi < 2; mi++) {
                int r = wr * 32 + mi * 16 + g;
                int c = kk * 8 + t4;
                ah[mi][0] = AsH[r * ASTR + c];
                ah[mi][1] = AsH[(r + 8) * ASTR + c];
                ah[mi][2] = AsH[r * ASTR + c + 4];
                ah[mi][3] = AsH[(r + 8) * ASTR + c + 4];
                al[mi][0] = AsL[r * ASTR + c];
                al[mi][1] = AsL[(r + 8) * ASTR + c];
                al[mi][2] = AsL[r * ASTR + c + 4];
                al[mi][3] = AsL[(r + 8) * ASTR + c + 4];
            }
#pragma unroll
            for (int ni = 0; ni < 8; ni++) {
                int cb = wc * 64 + ni * 8 + g;
                int k1 = kk * 8 + t4;
                unsigned bh0 = BsH[k1 * BSTR + cb];
                unsigned bh1 = BsH[(k1 + 4) * BSTR + cb];
                unsigned bl0 = BsL[k1 * BSTR + cb];
                unsigned bl1 = BsL[(k1 + 4) * BSTR + cb];
#pragma unroll
                for (int mi = 0; mi < 2; mi++) {
                    mma_tf32(acc[mi][ni], ah[mi], bh0, bh1);  // hi*hi
                    mma_tf32(acc[mi][ni], ah[mi], bl0, bl1);  // hi*lo
                    mma_tf32(acc[mi][ni], al[mi], bh0, bh1);  // lo*hi
                }
            }
        }
        if (kt + 1 < ktiles) {
            __syncthreads();
            stageSmem();
            __syncthreads();
        }
    }

    // epilogue
#pragma unroll
    for (int mi = 0; mi < 2; mi++) {
#pragma unroll
        for (int ni = 0; ni < 8; ni++) {
            int r0 = rowBase + wr * 32 + mi * 16 + g;
            int c0 = colBase + wc * 64 + ni * 8 + 2 * t4;
#pragma unroll
            for (int q = 0; q < 4; q++) {
                int r = r0 + (q >= 2 ? 8 : 0);
                int c = c0 + (q & 1);
                if (r < M && c < Nc) {
                    float v = acc[mi][ni][q];
                    size_t idx = (size_t)r * Nc + c;
                    if (EPI == 0) {
                        D[idx] = v + __ldg(bias + c);
                    } else if (EPI == 1) {
                        float t = v + __ldg(bias + c);
                        D[idx] = t >= 0.f ? t : alpha * t;
                    } else if (EPI == 2) {
                        float xv = X[idx];
                        float xi = xv >= 0.f ? xv : alpha * xv;
                        D[idx] = v + xi;
                    } else {
                        D[idx] = X[idx] + v + __ldg(bias + c);
                    }
                }
            }
        }
    }
}

// ============================================================================
extern "C" void kernel_launch(void* const* d_in, const int* in_sizes, int n_in,
                              void* d_out, int out_size)
{
    (void)in_sizes; (void)n_in; (void)out_size;

    const float* features  = (const float*)d_in[0];
    const float* label_emb = (const float*)d_in[1];
    const float* wa        = (const float*)d_in[2];
    const float* ba        = (const float*)d_in[3];
    const float* w0        = (const float*)d_in[4];
    const float* b0        = (const float*)d_in[5];
    const float* wg1       = (const float*)d_in[6];
    const float* wg2       = (const float*)d_in[7];
    const float* w_last    = (const float*)d_in[8];
    const float* b_last    = (const float*)d_in[9];
    const float* a_out     = (const float*)d_in[10];
    const float* wl0       = (const float*)d_in[11];
    const float* bl0       = (const float*)d_in[12];
    const float* wl1       = (const float*)d_in[13];
    const float* bl1       = (const float*)d_in[14];
    const float* wl2       = (const float*)d_in[15];
    const float* bl2       = (const float*)d_in[16];
    const float* wl3       = (const float*)d_in[17];
    const float* bl3       = (const float*)d_in[18];
    const float* a_lab     = (const float*)d_in[19];
    float* out = (float*)d_out;

    float *S1, *S2, *S3;
    cudaGetSymbolAddress((void**)&S1, g_S1);
    cudaGetSymbolAddress((void**)&S2, g_S2);
    cudaGetSymbolAddress((void**)&S3, g_S3);

    dim3 blk(256);
    dim3 gAtt((NROWS + 7) / 8);                                   // 8 warps/block
    dim3 g512((HIDD + BN - 1) / BN, (NROWS + BM - 1) / BM);       // (4, 782)
    dim3 g47(1, (NROWS + BM - 1) / BM);

    // attention -> right in S3 (N x 256)
    att_kernel<<<gAtt, blk>>>(features, wa, ba, S3);

    // label branch: S1/S2 ping-pong, final into out
    gemm_kernel<0,1><<<g512, blk>>>(label_emb, nullptr, wl0, bl0, S1, nullptr, a_lab, NROWS, HIDD, C_);
    gemm_kernel<0,1><<<g512, blk>>>(S1, nullptr, wl1, bl1, S2, nullptr, a_lab, NROWS, HIDD, HIDD);
    gemm_kernel<0,1><<<g512, blk>>>(S2, nullptr, wl2, bl2, S1, nullptr, a_lab, NROWS, HIDD, HIDD);
    gemm_kernel<0,0><<<g47 , blk>>>(S1, nullptr, wl3, bl3, out, nullptr, nullptr, NROWS, C_, HIDD);

    // feature branch
    // x0 = right@w0 + b0 -> S2 (this is both x and h0)
    gemm_kernel<0,0><<<g512, blk>>>(S3, nullptr, w0, b0, S2, nullptr, nullptr, NROWS, HIDD, F_);
    // x1 = (0.5*prelu(x0)+0.5*h0)@wg1 + prelu(x0) -> S1
    gemm_kernel<2,2><<<g512, blk>>>(S2, S2, wg1, nullptr, S1, S2, a_out, NROWS, HIDD, HIDD);
    // x2 = (0.5*prelu(x1)+0.5*h0)@wg2 + prelu(x1) -> S3
    gemm_kernel<2,2><<<g512, blk>>>(S1, S2, wg2, nullptr, S3, S1, a_out, NROWS, HIDD, HIDD);
    // out += prelu(x2)@w_last + b_last
    gemm_kernel<1,3><<<g47 , blk>>>(S3, nullptr, w_last, b_last, out, out, a_out, NROWS, C_, HIDD);
}